// round 9
// baseline (speedup 1.0000x reference)
#include <cuda_runtime.h>
#include <cstdint>

// EmbeddingWithDropout:
//   out[t, :] = weight[x[t], :] * ((u[x[t]] >= 0.1) ? 1/0.9 : 0)
// x: int32 [131072], weight: fp32 [100000,128], u: fp32 [100000]
// out: fp32 [131072, 128]

#define DROPOUT  0.1f
#define INV_KEEP (1.0f / (1.0f - DROPOUT))
#define TPW      8       // tokens per warp

// 256-bit gather with L2 evict-last (sm_100+: hint requires .v8.b32 form)
__device__ __forceinline__ void ldg_el_v8(const float* p, float r[8]) {
    uint32_t a0,a1,a2,a3,a4,a5,a6,a7;
    asm volatile("ld.global.nc.L2::evict_last.v8.b32 {%0,%1,%2,%3,%4,%5,%6,%7}, [%8];"
                 : "=r"(a0),"=r"(a1),"=r"(a2),"=r"(a3),
                   "=r"(a4),"=r"(a5),"=r"(a6),"=r"(a7)
                 : "l"(p));
    r[0]=__uint_as_float(a0); r[1]=__uint_as_float(a1);
    r[2]=__uint_as_float(a2); r[3]=__uint_as_float(a3);
    r[4]=__uint_as_float(a4); r[5]=__uint_as_float(a5);
    r[6]=__uint_as_float(a6); r[7]=__uint_as_float(a7);
}

__global__ void __launch_bounds__(256)
emb_dropout_kernel(const int4* __restrict__ x4,
                   const float* __restrict__ weight,
                   const float* __restrict__ u,
                   float* __restrict__ out,
                   int n_tokens)
{
    const int lane    = threadIdx.x & 31;
    const int half    = lane >> 4;        // 0: even token of pair, 1: odd
    const int sublane = lane & 15;        // 16 lanes x 8 floats = 128 floats/row
    const int warp_g  = (blockIdx.x * (blockDim.x >> 5)) + (threadIdx.x >> 5);
    const int token0  = warp_g * TPW;
    if (token0 >= n_tokens) return;

    // Phase 1: 8 indices via two int4 loads (warp-uniform broadcast)
    int4 ia = __ldg(x4 + (token0 >> 2));
    int4 ib = __ldg(x4 + (token0 >> 2) + 1);
    const int i0=ia.x, i1=ia.y, i2=ia.z, i3=ia.w;
    const int i4=ib.x, i5=ib.y, i6=ib.z, i7=ib.w;

    // Phase 2: 8 independent per-row uniforms (L1-broadcast within warp)
    float u0=__ldg(u+i0), u1=__ldg(u+i1), u2=__ldg(u+i2), u3=__ldg(u+i3);
    float u4=__ldg(u+i4), u5=__ldg(u+i5), u6=__ldg(u+i6), u7=__ldg(u+i7);

    // Phase 3: 4 independent 256-bit gathers; each covers 2 rows (2 tokens)
    // pair p: lanes 0-15 -> token 2p, lanes 16-31 -> token 2p+1
    const int idp0 = half ? i1 : i0;
    const int idp1 = half ? i3 : i2;
    const int idp2 = half ? i5 : i4;
    const int idp3 = half ? i7 : i6;
    const int foff = sublane * 8;         // float offset within row

    float v0[8], v1[8], v2[8], v3[8];
    ldg_el_v8(weight + (size_t)idp0 * 128 + foff, v0);
    ldg_el_v8(weight + (size_t)idp1 * 128 + foff, v1);
    ldg_el_v8(weight + (size_t)idp2 * 128 + foff, v2);
    ldg_el_v8(weight + (size_t)idp3 * 128 + foff, v3);

    // Phase 4: per-token scale, streaming 128-bit stores (evict-first)
    const float s0 = ((half ? u1 : u0) >= DROPOUT) ? INV_KEEP : 0.0f;
    const float s1 = ((half ? u3 : u2) >= DROPOUT) ? INV_KEEP : 0.0f;
    const float s2 = ((half ? u5 : u4) >= DROPOUT) ? INV_KEEP : 0.0f;
    const float s3 = ((half ? u7 : u6) >= DROPOUT) ? INV_KEEP : 0.0f;

#define STORE_PAIR(P, V, S)                                                   \
    do {                                                                       \
        float4* dst = (float4*)(out + (size_t)(token0 + 2*(P) + half)*128 + foff); \
        float4 lo = make_float4((V)[0]*(S), (V)[1]*(S), (V)[2]*(S), (V)[3]*(S)); \
        float4 hi = make_float4((V)[4]*(S), (V)[5]*(S), (V)[6]*(S), (V)[7]*(S)); \
        __stcs(dst,     lo);                                                   \
        __stcs(dst + 1, hi);                                                   \
    } while (0)

    STORE_PAIR(0, v0, s0);
    STORE_PAIR(1, v1, s1);
    STORE_PAIR(2, v2, s2);
    STORE_PAIR(3, v3, s3);
#undef STORE_PAIR
}

extern "C" void kernel_launch(void* const* d_in, const int* in_sizes, int n_in,
                              void* d_out, int out_size)
{
    const int4*  x4     = (const int4*)d_in[0];
    const float* weight = (const float*)d_in[1];
    const float* u      = (const float*)d_in[2];
    float*       out    = (float*)d_out;

    int n_tokens = in_sizes[0];                  // 131072 (divisible by TPW)
    int threads  = 256;                          // 8 warps/block
    int tokens_per_block = (threads >> 5) * TPW; // 64
    int blocks = (n_tokens + tokens_per_block - 1) / tokens_per_block;

    emb_dropout_kernel<<<blocks, threads>>>(x4, weight, u, out, n_tokens);
}

// round 10
// speedup vs baseline: 1.4813x; 1.4813x over previous
#include <cuda_runtime.h>
#include <cstdint>

// EmbeddingWithDropout:
//   out[t, :] = weight[x[t], :] * ((u[x[t]] >= 0.1) ? 1/0.9 : 0)
// x: int32 [131072], weight: fp32 [100000,128], u: fp32 [100000]
// out: fp32 [131072, 128]

#define DROPOUT  0.1f
#define INV_KEEP (1.0f / (1.0f - DROPOUT))
#define DIM_VEC  32      // 128 floats = 32 float4 per row
#define TPW      8       // tokens per warp

__global__ void __launch_bounds__(256)
emb_dropout_kernel(const int4* __restrict__ x4,
                   const float4* __restrict__ weight,
                   const float* __restrict__ u,
                   float4* __restrict__ out,
                   int n_tokens)
{
    const int lane   = threadIdx.x & 31;
    const int warp_g = (blockIdx.x * (blockDim.x >> 5)) + (threadIdx.x >> 5);
    const int token0 = warp_g * TPW;
    if (token0 >= n_tokens) return;

    // Phase 1: 8 indices via two int4 loads (warp-uniform broadcast)
    int4 ia = __ldg(x4 + (token0 >> 2));
    int4 ib = __ldg(x4 + (token0 >> 2) + 1);
    int idx[TPW] = {ia.x, ia.y, ia.z, ia.w, ib.x, ib.y, ib.z, ib.w};

    // Phase 2: 8 independent per-row uniforms (batched; L1 broadcast)
    float uu[TPW];
#pragma unroll
    for (int t = 0; t < TPW; t++)
        uu[t] = __ldg(u + idx[t]);

    // Phase 3: 8 independent 128-bit row gathers (full row per warp, MLP=8)
    float4 v[TPW];
#pragma unroll
    for (int t = 0; t < TPW; t++)
        v[t] = __ldg(weight + (size_t)idx[t] * DIM_VEC + lane);

    // Phase 4: scale + streaming stores (evict-first; keep table in L2)
#pragma unroll
    for (int t = 0; t < TPW; t++) {
        float s = (uu[t] >= DROPOUT) ? INV_KEEP : 0.0f;
        float4 r = v[t];
        r.x *= s; r.y *= s; r.z *= s; r.w *= s;
        __stcs(out + (size_t)(token0 + t) * DIM_VEC + lane, r);
    }
}

extern "C" void kernel_launch(void* const* d_in, const int* in_sizes, int n_in,
                              void* d_out, int out_size)
{
    const int4*   x4     = (const int4*)d_in[0];
    const float4* weight = (const float4*)d_in[1];
    const float*  u      = (const float*)d_in[2];
    float4*       out    = (float4*)d_out;

    int n_tokens = in_sizes[0];                  // 131072 (divisible by TPW)
    int threads  = 256;                          // 8 warps/block
    int tokens_per_block = (threads >> 5) * TPW; // 64
    int blocks = (n_tokens + tokens_per_block - 1) / tokens_per_block;

    emb_dropout_kernel<<<blocks, threads>>>(x4, weight, u, out, n_tokens);
}